// round 9
// baseline (speedup 1.0000x reference)
#include <cuda_runtime.h>
#include <cstdint>

// Problem constants: x is (16384, 2048) fp32, angles (2048,) fp32, out (16384, 2048) fp32.
constexpr int NN = 2048;   // row length n
constexpr int T  = 256;    // threads per block
constexpr int E  = 8;      // elements per thread (T*E == NN)
constexpr int R  = 8;      // rows per block (4 pairs, cp.async pipelined)
constexpr int PAIRS = R / 2;
constexpr int PAIR_FLOATS = 2 * NN;                       // 4096 floats / pair

// Precomputed tables (device globals: no dynamic allocation allowed).
__device__ __align__(16) float g_c[NN];
__device__ __align__(16) float g_s[NN];
// Row-independent scan weights (P-side of the affine scan):
__device__ float g_W5[5][T];   // warp suffix-scan jump weights (prod_{i<d} P_{t+i}, 0 past warp end)
__device__ float g_Pe[T];      // warp-exclusive product (lanes > lid, same warp)
__device__ float g_PfA[T];     // block-exclusive product (threads > t)
__device__ float g_Pw[8];      // per-warp total products

// ---------------- cp.async helpers ----------------
__device__ __forceinline__ uint32_t smem_u32(const void* p) {
    return (uint32_t)__cvta_generic_to_shared(p);
}
__device__ __forceinline__ void cp_async16(uint32_t dst, const void* src) {
    asm volatile("cp.async.cg.shared.global [%0], [%1], 16;"
                 :: "r"(dst), "l"(src) : "memory");
}
__device__ __forceinline__ void cp_commit() {
    asm volatile("cp.async.commit_group;" ::: "memory");
}
template <int N>
__device__ __forceinline__ void cp_wait() {
    asm volatile("cp.async.wait_group %0;" :: "n"(N) : "memory");
}

// XOR swizzle on 16B granules: g -> g ^ ((g>>3)&1).
// Store requests (consecutive granules) stay conflict-free; the stride-2
// granule reads (thread t reads granules 2t, 2t+1) become all-distinct
// banks per 8-thread LDS phase. Involution (self-inverse).
__device__ __forceinline__ int swz(int g) { return g ^ ((g >> 3) & 1); }
// float index of element e inside a swizzled pair-buffer
__device__ __forceinline__ int swadr(int e) { return (swz(e >> 2) << 2) | (e & 3); }

// Fused prep, one block: sincos for all angles + all P-side scan constants.
__global__ void prep_kernel(const float* __restrict__ ang) {
    __shared__ float Slev[T];
    __shared__ float spw[8];
    const int t = threadIdx.x, lid = t & 31, w = t >> 5, lo = t * E;

    float ssl[E];
#pragma unroll
    for (int m = 0; m < E; ++m) {
        float s, c;
        sincosf(ang[lo + m], &s, &c);
        g_c[lo + m] = c;
        g_s[lo + m] = s;
        ssl[m] = s;
    }

    float P = 1.f;
#pragma unroll
    for (int m = E - 1; m >= 0; --m) {
        if (lo + m == NN - 1) continue;       // k = N-1 is the seed, not a scan step
        P *= -ssl[m];
    }

    // W levels by doubling: S_{2h}[t] = S_h[t] * S_h[t+h]   (0 past warp end)
    float S = P;
    g_W5[0][t] = (lid + 1 < 32) ? S : 0.f;
    for (int di = 1; di < 5; ++di) {
        const int d = 1 << di, half = d >> 1;
        __syncthreads();
        Slev[t] = S;
        __syncthreads();
        float part = (lid + half < 32) ? Slev[t + half] : 0.f;
        S *= part;
        g_W5[di][t] = (lid + d < 32) ? S : 0.f;
    }

    // warp inclusive suffix scan of P (prod over lanes >= lid)
    float Pscan = P;
#pragma unroll
    for (int d = 1; d < 32; d <<= 1) {
        float tmp = __shfl_down_sync(0xffffffffu, Pscan, d);
        if (lid + d < 32) Pscan *= tmp;
    }
    float Pe = __shfl_down_sync(0xffffffffu, Pscan, 1);
    if (lid == 31) Pe = 1.f;
    g_Pe[t] = Pe;
    if (lid == 0) spw[w] = Pscan;             // warp total
    __syncthreads();

    float Pf = Pe;
    for (int w2 = w + 1; w2 < 8; ++w2) Pf *= spw[w2];
    g_PfA[t] = Pf;
    if (t < 8) g_Pw[t] = spw[t];
}

// y_row = G_0 (G_1 (... (G_{N-1} x_row))). First-order affine recurrence on the
// carry; Q-only weighted warp suffix scan (P-side precomputed). Pairs of rows
// stream through double-buffered, XOR-swizzled smem via per-thread cp.async:
// DRAM latency overlaps compute with zero register cost and conflict-free LDS.
__global__ void __launch_bounds__(T, 4) givens_kernel(const float* __restrict__ x,
                                                      float* __restrict__ y) {
    __shared__ __align__(16) float buf[2][PAIR_FLOATS];   // two 16 KB pair buffers
    __shared__ __align__(16) float wtQ[2][2][8];          // [buffer][row][warp]

    const int t   = threadIdx.x;
    const int lid = t & 31;
    const int w   = t >> 5;
    const int lo  = t * E;
    const long base = (long)blockIdx.x * R;

    // Precompute swizzled store addresses for this thread's 4 copies (j = 0..3):
    // logical granule L = t + 256*j  ->  physical swz(L)*16 bytes.
    uint32_t dst0 = smem_u32(buf[0]);
    uint32_t dst1 = smem_u32(buf[1]);
    uint32_t soff[4];
#pragma unroll
    for (int j = 0; j < 4; ++j) soff[j] = (uint32_t)swz(t + 256 * j) * 16u;

    const float* gsrc = x + base * NN + t * 4;            // float4 f = t + 256j

    // ---- prologue: async-copy pairs 0 and 1 (two groups) ----
#pragma unroll
    for (int j = 0; j < 4; ++j) cp_async16(dst0 + soff[j], gsrc + 1024 * j);
    cp_commit();
#pragma unroll
    for (int j = 0; j < 4; ++j) cp_async16(dst1 + soff[j], gsrc + PAIR_FLOATS + 1024 * j);
    cp_commit();

    // ---- per-block constants (overlap with the first DMAs) ----
    float cc[E], ss[E];
    {
        float4 c0 = reinterpret_cast<const float4*>(g_c + lo)[0];
        float4 c1 = reinterpret_cast<const float4*>(g_c + lo)[1];
        cc[0] = c0.x; cc[1] = c0.y; cc[2] = c0.z; cc[3] = c0.w;
        cc[4] = c1.x; cc[5] = c1.y; cc[6] = c1.z; cc[7] = c1.w;
        float4 s0 = reinterpret_cast<const float4*>(g_s + lo)[0];
        float4 s1 = reinterpret_cast<const float4*>(g_s + lo)[1];
        ss[0] = s0.x; ss[1] = s0.y; ss[2] = s0.z; ss[3] = s0.w;
        ss[4] = s1.x; ss[5] = s1.y; ss[6] = s1.z; ss[7] = s1.w;
    }
    float W[5];
#pragma unroll
    for (int di = 0; di < 5; ++di) W[di] = g_W5[di][t];
    const float Pe = g_Pe[t];
    const float Pf = g_PfA[t];
    const float pw1 = g_Pw[1], pw2 = g_Pw[2], pw3 = g_Pw[3],
                pw4 = g_Pw[4], pw5 = g_Pw[5], pw6 = g_Pw[6];
    const float cN = g_c[NN - 1];
    const float sN = g_s[NN - 1];

    const bool warp_head = (lid == 0) && (w > 0);
    float cprev = 0.f, sprev = 0.f;
    if (warp_head) { cprev = g_c[lo - 1]; sprev = g_s[lo - 1]; }

    // Swizzled float-index offsets for this thread's chunk reads:
    const int rA0 = swz(2 * t) << 2;          // row A elems lo..lo+3
    const int rA1 = swz(2 * t + 1) << 2;      // row A elems lo+4..lo+7
    const int rB0 = swz(512 + 2 * t) << 2;    // row B elems lo..lo+3
    const int rB1 = swz(513 + 2 * t) << 2;    // row B elems lo+4..lo+7
    const int aX0A  = swadr(0),        aXn1A = swadr(NN - 1);
    const int aX0B  = swadr(NN),       aXn1B = swadr(2 * NN - 1);
    const int aXpvA = warp_head ? swadr(lo - 1)      : 0;
    const int aXpvB = warp_head ? swadr(NN + lo - 1) : 0;

    cp_wait<1>();          // my pair-0 copies done
    __syncthreads();       // everyone's pair-0 copies done

#pragma unroll 1
    for (int p = 0; p < PAIRS; ++p) {
        const int bi = p & 1;
        const float* bb = buf[bi];

        float xa[E], xb[E];
        {
            float4 a0 = *reinterpret_cast<const float4*>(bb + rA0);
            float4 a1 = *reinterpret_cast<const float4*>(bb + rA1);
            float4 b0 = *reinterpret_cast<const float4*>(bb + rB0);
            float4 b1 = *reinterpret_cast<const float4*>(bb + rB1);
            xa[0] = a0.x; xa[1] = a0.y; xa[2] = a0.z; xa[3] = a0.w;
            xa[4] = a1.x; xa[5] = a1.y; xa[6] = a1.z; xa[7] = a1.w;
            xb[0] = b0.x; xb[1] = b0.y; xb[2] = b0.z; xb[3] = b0.w;
            xb[4] = b1.x; xb[5] = b1.y; xb[6] = b1.z; xb[7] = b1.w;
        }
        // Boundary values straight from the tile (broadcast / tiny predicated LDS):
        const float x0A = bb[aX0A], xn1A = bb[aXn1A];
        const float x0B = bb[aX0B], xn1B = bb[aXn1B];
        const float xpvA = warp_head ? bb[aXpvA] : 0.f;
        const float xpvB = warp_head ? bb[aXpvB] : 0.f;

        const float seedA = fmaf(cN, xn1A, -sN * x0A);    // prev_{N-1}
        const float seedB = fmaf(cN, xn1B, -sN * x0B);
        if (t == 0) {
            xa[0] = fmaf(sN, xn1A, cN * x0A);             // X_0 fix (thread 0's Q unused)
            xb[0] = fmaf(sN, xn1B, cN * x0B);
        }

        // ---- Q composition for both rows (independent chains) ----
        float QA = 0.f, QB = 0.f;
#pragma unroll
        for (int m = E - 1; m >= 0; --m) {
            if (lo + m == NN - 1) continue;               // seed step
            QA = fmaf(-ss[m], QA, cc[m] * xa[m]);
            QB = fmaf(-ss[m], QB, cc[m] * xb[m]);
        }

        // ---- Q-only weighted warp suffix scan, both rows interleaved ----
#pragma unroll
        for (int di = 0, d = 1; di < 5; ++di, d <<= 1) {
            float qa2 = __shfl_down_sync(0xffffffffu, QA, d);
            float qb2 = __shfl_down_sync(0xffffffffu, QB, d);
            QA = fmaf(W[di], qa2, QA);
            QB = fmaf(W[di], qb2, QB);
        }
        float QeA = __shfl_down_sync(0xffffffffu, QA, 1);
        float QeB = __shfl_down_sync(0xffffffffu, QB, 1);
        if (lid == 31) { QeA = 0.f; QeB = 0.f; }

        if (lid == 0) { wtQ[bi][0][w] = QA; wtQ[bi][1][w] = QB; }
        __syncthreads();      // scan totals ready; also proves buf[bi] fully read

        // ---- refill this buffer for pair p+2 (copies fly during the epilogue) ----
        if (p + 2 < PAIRS) {
            const float* src2 = gsrc + (long)(p + 2) * PAIR_FLOATS;
            const uint32_t dstb = bi ? dst1 : dst0;
#pragma unroll
            for (int j = 0; j < 4; ++j) cp_async16(dstb + soff[j], src2 + 1024 * j);
            cp_commit();
        }

        // ---- cross-warp Horner over later warps, both rows ----
        float4 qa0 = *reinterpret_cast<const float4*>(&wtQ[bi][0][0]);
        float4 qa1 = *reinterpret_cast<const float4*>(&wtQ[bi][0][4]);
        float4 qb0 = *reinterpret_cast<const float4*>(&wtQ[bi][1][0]);
        float4 qb1 = *reinterpret_cast<const float4*>(&wtQ[bi][1][4]);
        float QpA = 0.f, QpB = 0.f;
        if (w < 7) { QpA = qa1.w;                 QpB = qb1.w; }
        if (w < 6) { QpA = fmaf(pw6, QpA, qa1.z); QpB = fmaf(pw6, QpB, qb1.z); }
        if (w < 5) { QpA = fmaf(pw5, QpA, qa1.y); QpB = fmaf(pw5, QpB, qb1.y); }
        if (w < 4) { QpA = fmaf(pw4, QpA, qa1.x); QpB = fmaf(pw4, QpB, qb1.x); }
        if (w < 3) { QpA = fmaf(pw3, QpA, qa0.w); QpB = fmaf(pw3, QpB, qb0.w); }
        if (w < 2) { QpA = fmaf(pw2, QpA, qa0.z); QpB = fmaf(pw2, QpB, qb0.z); }
        if (w < 1) { QpA = fmaf(pw1, QpA, qa0.y); QpB = fmaf(pw1, QpB, qb0.y); }

        float prevA = fmaf(Pf, seedA, fmaf(Pe, QpA, QeA));
        float prevB = fmaf(Pf, seedB, fmaf(Pe, QpB, QeB));

        // ---- replay in place, both rows; ends with prev = prev_lo ----
#pragma unroll
        for (int m = E - 1; m >= 0; --m) {
            if (lo + m == NN - 1) { xa[m] = 0.f; xb[m] = 0.f; continue; }
            const float xmA = xa[m], xmB = xb[m];
            xa[m] = fmaf(ss[m], xmA, cc[m] * prevA);
            prevA = fmaf(-ss[m], prevA, cc[m] * xmA);
            xb[m] = fmaf(ss[m], xmB, cc[m] * prevB);
            prevB = fmaf(-ss[m], prevB, cc[m] * xmB);
        }

        // out[lo]: lanes 1-31 take previous lane's xv[7]; warp heads recompute;
        // thread 0 has it as prev_0.
        float carryA = __shfl_up_sync(0xffffffffu, xa[E - 1], 1);
        float carryB = __shfl_up_sync(0xffffffffu, xb[E - 1], 1);
        if (t == 0) {
            carryA = prevA; carryB = prevB;
        } else if (warp_head) {
            carryA = fmaf(sprev, xpvA, cprev * prevA);
            carryB = fmaf(sprev, xpvB, cprev * prevB);
        }

        float* yrA = y + (base + 2 * p) * NN;
        float* yrB = yrA + NN;
        float4 oa0, oa1, ob0, ob1;
        oa0.x = carryA; oa0.y = xa[0]; oa0.z = xa[1]; oa0.w = xa[2];
        oa1.x = xa[3];  oa1.y = xa[4]; oa1.z = xa[5]; oa1.w = xa[6];
        ob0.x = carryB; ob0.y = xb[0]; ob0.z = xb[1]; ob0.w = xb[2];
        ob1.x = xb[3];  ob1.y = xb[4]; ob1.z = xb[5]; ob1.w = xb[6];
        __stcs(reinterpret_cast<float4*>(yrA + lo), oa0);
        __stcs(reinterpret_cast<float4*>(yrA + lo) + 1, oa1);
        __stcs(reinterpret_cast<float4*>(yrB + lo), ob0);
        __stcs(reinterpret_cast<float4*>(yrB + lo) + 1, ob1);

        // ---- make pair p+1 visible for the next iteration ----
        if (p + 1 < PAIRS) {
            if (p + 2 < PAIRS) cp_wait<1>(); else cp_wait<0>();
            __syncthreads();
        }
    }
}

// Remainder rows (rows % R != 0): one row per block, direct loads.
// Not triggered for B=16384, kept for generality.
__global__ void __launch_bounds__(T) givens_tail_kernel(const float* __restrict__ x,
                                                        float* __restrict__ y,
                                                        int row0) {
    __shared__ __align__(16) float wtQ[8];
    __shared__ float sxe[8];
    __shared__ float sx01[2];

    const int t = threadIdx.x, lid = t & 31, w = t >> 5, lo = t * E;
    const long row = row0 + blockIdx.x;
    const float* xr = x + row * NN;
    float* yr = y + row * NN;

    float cc[E], ss[E], xv[E];
#pragma unroll
    for (int m = 0; m < E; ++m) {
        cc[m] = g_c[lo + m]; ss[m] = g_s[lo + m]; xv[m] = xr[lo + m];
    }
    float W[5];
#pragma unroll
    for (int di = 0; di < 5; ++di) W[di] = g_W5[di][t];
    const float Pe = g_Pe[t], Pf = g_PfA[t];
    const float cN = g_c[NN - 1], sN = g_s[NN - 1];
    const bool warp_head = (lid == 0) && (w > 0);

    if (lid == 31) sxe[w] = xv[7];
    if (t == 0)    sx01[0] = xv[0];
    if (t == T-1)  sx01[1] = xv[7];

    float Q = 0.f;
#pragma unroll
    for (int m = E - 1; m >= 0; --m) {
        if (lo + m == NN - 1) continue;
        Q = fmaf(-ss[m], Q, cc[m] * xv[m]);
    }
#pragma unroll
    for (int di = 0, d = 1; di < 5; ++di, d <<= 1) {
        float q2 = __shfl_down_sync(0xffffffffu, Q, d);
        Q = fmaf(W[di], q2, Q);
    }
    float Qe = __shfl_down_sync(0xffffffffu, Q, 1);
    if (lid == 31) Qe = 0.f;
    if (lid == 0) wtQ[w] = Q;
    __syncthreads();

    float Qp = 0.f;
    for (int w2 = 7; w2 > w; --w2) Qp = fmaf(g_Pw[w2], Qp, wtQ[w2]);
    const float x0 = sx01[0], xn1 = sx01[1];
    const float seed = fmaf(cN, xn1, -sN * x0);
    if (t == 0) xv[0] = fmaf(sN, xn1, cN * x0);
    float prev = fmaf(Pf, seed, fmaf(Pe, Qp, Qe));

#pragma unroll
    for (int m = E - 1; m >= 0; --m) {
        if (lo + m == NN - 1) { xv[m] = 0.f; continue; }
        const float xm = xv[m];
        xv[m] = fmaf(ss[m], xm, cc[m] * prev);
        prev  = fmaf(-ss[m], prev, cc[m] * xm);
    }
    float carry = __shfl_up_sync(0xffffffffu, xv[E - 1], 1);
    if (t == 0)         carry = prev;
    else if (warp_head) carry = fmaf(g_s[lo - 1], sxe[w - 1], g_c[lo - 1] * prev);

    float4 o0, o1;
    o0.x = carry; o0.y = xv[0]; o0.z = xv[1]; o0.w = xv[2];
    o1.x = xv[3]; o1.y = xv[4]; o1.z = xv[5]; o1.w = xv[6];
    reinterpret_cast<float4*>(yr + lo)[0] = o0;
    reinterpret_cast<float4*>(yr + lo)[1] = o1;
}

extern "C" void kernel_launch(void* const* d_in, const int* in_sizes, int n_in,
                              void* d_out, int out_size) {
    const float* x   = (const float*)d_in[0];   // (B, N) fp32
    const float* ang = (const float*)d_in[1];   // (N,)  fp32
    float* y = (float*)d_out;                   // (B, N) fp32

    prep_kernel<<<1, T>>>(ang);

    const int rows = out_size / NN;             // B = 16384
    const int full = rows / R;                  // 2048 full blocks
    if (full > 0) givens_kernel<<<full, T>>>(x, y);
    const int rem = rows - full * R;
    if (rem > 0) givens_tail_kernel<<<rem, T>>>(x, y, full * R);
}

// round 10
// speedup vs baseline: 1.1939x; 1.1939x over previous
#include <cuda_runtime.h>
#include <cstdint>

// Problem constants: x is (16384, 2048) fp32, angles (2048,) fp32, out (16384, 2048) fp32.
constexpr int NN = 2048;   // row length n
constexpr int T  = 256;    // threads per block
constexpr int E  = 8;      // elements per thread (T*E == NN)
constexpr int R  = 4;      // rows per block (processed as 2 pairs)

// y_row = G_0 (G_1 (... (G_{N-1} x_row))). First-order affine recurrence on the
// carry; Q-only weighted warp suffix scan. ALL row-independent constants
// (sin/cos, P-side scan weights) are derived inline per block with log-depth
// shuffle scans — no prep kernel, no tables, no launch dependency stall.
// Two rows per iteration: independent scan chains interleave (hiding SHFL
// latency), loads/stores pair up (2x MLP), one barrier serves two rows.
__global__ void __launch_bounds__(T, 4) givens_kernel(const float* __restrict__ x,
                                                      const float* __restrict__ ang,
                                                      float* __restrict__ y,
                                                      int rows) {
    __shared__ __align__(16) float wtQ[2][2][8];  // [pair parity][row in pair][warp]
    __shared__ float sxe[2][2][8];                // lane-31 x[lo+7] per warp
    __shared__ float sx01[2][2][2];               // x[0], x[N-1]
    __shared__ float spw[8];                      // per-warp P totals
    __shared__ float scs[8][2];                   // per-warp tail coefficient (c,s at lo+7 of lane 31)
    __shared__ float stail[2];                    // cN, sN  (coefficients at N-1)

    const int t   = threadIdx.x;
    const int lid = t & 31;
    const int w   = t >> 5;
    const int lo  = t * E;
    const long base = (long)blockIdx.x * R;
    if (base >= rows) return;

    // ================= inline prep (row-independent, ~200 instr) =================
    float cc[E], ss[E];
    {
        float4 a0 = reinterpret_cast<const float4*>(ang + lo)[0];
        float4 a1 = reinterpret_cast<const float4*>(ang + lo)[1];
        __sincosf(a0.x, &ss[0], &cc[0]);
        __sincosf(a0.y, &ss[1], &cc[1]);
        __sincosf(a0.z, &ss[2], &cc[2]);
        __sincosf(a0.w, &ss[3], &cc[3]);
        __sincosf(a1.x, &ss[4], &cc[4]);
        __sincosf(a1.y, &ss[5], &cc[5]);
        __sincosf(a1.z, &ss[6], &cc[6]);
        __sincosf(a1.w, &ss[7], &cc[7]);
    }

    // Per-thread P = prod of (-s_k) over this chunk (k = N-1 is the seed, skipped).
    float P = 1.f;
#pragma unroll
    for (int m = E - 1; m >= 0; --m) {
        if (lo + m == NN - 1) continue;
        P *= -ss[m];
    }

    // Warp suffix-scan jump weights by shuffle product-doubling:
    // W[di] = prod_{i < 2^di} P_{lid+i}  (0 past warp end).
    float W[5];
    {
        float S = P;
        W[0] = (lid + 1 < 32) ? S : 0.f;
#pragma unroll
        for (int di = 1; di < 5; ++di) {
            const int h = 1 << (di - 1);
            float Sn = __shfl_down_sync(0xffffffffu, S, h);
            S *= (lid + h < 32) ? Sn : 0.f;
            W[di] = (lid + (1 << di) < 32) ? S : 0.f;
        }
    }

    // Warp inclusive suffix scan of P -> Pe (exclusive), Pw (warp totals).
    float Pscan = P;
#pragma unroll
    for (int d = 1; d < 32; d <<= 1) {
        float tmp = __shfl_down_sync(0xffffffffu, Pscan, d);
        if (lid + d < 32) Pscan *= tmp;
    }
    float Pe = __shfl_down_sync(0xffffffffu, Pscan, 1);
    if (lid == 31) Pe = 1.f;

    if (lid == 0)  spw[w] = Pscan;                       // warp total product
    if (lid == 31) { scs[w][0] = cc[7]; scs[w][1] = ss[7]; }
    if (t == T - 1) { stail[0] = cc[7]; stail[1] = ss[7]; }
    __syncthreads();                                     // one barrier for all of prep

    float Pf = Pe;
    for (int w2 = w + 1; w2 < 8; ++w2) Pf *= spw[w2];    // block-exclusive product
    const float pw1 = spw[1], pw2 = spw[2], pw3 = spw[3],
                pw4 = spw[4], pw5 = spw[5], pw6 = spw[6];
    const float cN = stail[0];
    const float sN = stail[1];

    // Warp-head lanes (lane 0 of warps 1..7) rebuild out[lo] locally:
    // out[lo] = s[lo-1]*x[lo-1] + c[lo-1]*prev_lo.
    const bool warp_head = (lid == 0) && (w > 0);
    float cprev = 0.f, sprev = 0.f;
    if (warp_head) { cprev = scs[w - 1][0]; sprev = scs[w - 1][1]; }

    // ================= main loop: two rows per iteration =================
#pragma unroll 1
    for (int r = 0; r < R; r += 2) {
        if (base + r >= rows) break;
        const bool hasB = (base + r + 1 < rows);
        const int buf = (r >> 1) & 1;
        const float* xrA = x + (base + r) * NN;
        const float* xrB = hasB ? (x + (base + r + 1) * NN) : xrA;

        // ---- loads for both rows (4 LDG.128 in flight) ----
        float xa[E], xb[E];
        {
            float4 a0 = __ldcs(reinterpret_cast<const float4*>(xrA + lo));
            float4 a1 = __ldcs(reinterpret_cast<const float4*>(xrA + lo) + 1);
            float4 b0 = __ldcs(reinterpret_cast<const float4*>(xrB + lo));
            float4 b1 = __ldcs(reinterpret_cast<const float4*>(xrB + lo) + 1);
            xa[0] = a0.x; xa[1] = a0.y; xa[2] = a0.z; xa[3] = a0.w;
            xa[4] = a1.x; xa[5] = a1.y; xa[6] = a1.z; xa[7] = a1.w;
            xb[0] = b0.x; xb[1] = b0.y; xb[2] = b0.z; xb[3] = b0.w;
            xb[4] = b1.x; xb[5] = b1.y; xb[6] = b1.z; xb[7] = b1.w;
        }
        // Boundary exchange through smem (pre-barrier writes):
        if (lid == 31) { sxe[buf][0][w] = xa[7]; sxe[buf][1][w] = xb[7]; }
        if (t == 0)    { sx01[buf][0][0] = xa[0]; sx01[buf][1][0] = xb[0]; }
        if (t == T-1)  { sx01[buf][0][1] = xa[7]; sx01[buf][1][1] = xb[7]; }

        // ---- Q composition for both rows (independent chains) ----
        // Thread 0's Q uses the UNcorrected x[0]; that Q is consumed by nobody.
        float QA = 0.f, QB = 0.f;
#pragma unroll
        for (int m = E - 1; m >= 0; --m) {
            if (lo + m == NN - 1) continue;            // seed step
            QA = fmaf(-ss[m], QA, cc[m] * xa[m]);
            QB = fmaf(-ss[m], QB, cc[m] * xb[m]);
        }

        // ---- Q-only weighted warp suffix scan, both rows interleaved ----
#pragma unroll
        for (int di = 0, d = 1; di < 5; ++di, d <<= 1) {
            float qa2 = __shfl_down_sync(0xffffffffu, QA, d);
            float qb2 = __shfl_down_sync(0xffffffffu, QB, d);
            QA = fmaf(W[di], qa2, QA);
            QB = fmaf(W[di], qb2, QB);
        }
        float QeA = __shfl_down_sync(0xffffffffu, QA, 1);
        float QeB = __shfl_down_sync(0xffffffffu, QB, 1);
        if (lid == 31) { QeA = 0.f; QeB = 0.f; }

        if (lid == 0) { wtQ[buf][0][w] = QA; wtQ[buf][1][w] = QB; }
        __syncthreads();                                // ONE barrier for two rows

        // ---- cross-warp Horner over later warps, both rows ----
        float4 qa0 = *reinterpret_cast<const float4*>(&wtQ[buf][0][0]);
        float4 qa1 = *reinterpret_cast<const float4*>(&wtQ[buf][0][4]);
        float4 qb0 = *reinterpret_cast<const float4*>(&wtQ[buf][1][0]);
        float4 qb1 = *reinterpret_cast<const float4*>(&wtQ[buf][1][4]);
        float QpA = 0.f, QpB = 0.f;
        if (w < 7) { QpA = qa1.w;                 QpB = qb1.w; }
        if (w < 6) { QpA = fmaf(pw6, QpA, qa1.z); QpB = fmaf(pw6, QpB, qb1.z); }
        if (w < 5) { QpA = fmaf(pw5, QpA, qa1.y); QpB = fmaf(pw5, QpB, qb1.y); }
        if (w < 4) { QpA = fmaf(pw4, QpA, qa1.x); QpB = fmaf(pw4, QpB, qb1.x); }
        if (w < 3) { QpA = fmaf(pw3, QpA, qa0.w); QpB = fmaf(pw3, QpB, qb0.w); }
        if (w < 2) { QpA = fmaf(pw2, QpA, qa0.z); QpB = fmaf(pw2, QpB, qb0.z); }
        if (w < 1) { QpA = fmaf(pw1, QpA, qa0.y); QpB = fmaf(pw1, QpB, qb0.y); }

        const float x0A  = sx01[buf][0][0], xn1A = sx01[buf][0][1];
        const float x0B  = sx01[buf][1][0], xn1B = sx01[buf][1][1];
        const float seedA = fmaf(cN, xn1A, -sN * x0A);  // prev_{N-1}
        const float seedB = fmaf(cN, xn1B, -sN * x0B);
        if (t == 0) {
            xa[0] = fmaf(sN, xn1A, cN * x0A);           // X_0 fix before replay
            xb[0] = fmaf(sN, xn1B, cN * x0B);
        }

        float prevA = fmaf(Pf, seedA, fmaf(Pe, QpA, QeA));
        float prevB = fmaf(Pf, seedB, fmaf(Pe, QpB, QeB));

        // ---- replay in place, both rows; ends with prev = prev_lo ----
#pragma unroll
        for (int m = E - 1; m >= 0; --m) {
            if (lo + m == NN - 1) { xa[m] = 0.f; xb[m] = 0.f; continue; }
            const float xmA = xa[m], xmB = xb[m];
            xa[m] = fmaf(ss[m], xmA, cc[m] * prevA);
            prevA = fmaf(-ss[m], prevA, cc[m] * xmA);
            xb[m] = fmaf(ss[m], xmB, cc[m] * prevB);
            prevB = fmaf(-ss[m], prevB, cc[m] * xmB);
        }

        // out[lo]: lanes 1-31 take previous lane's xv[7]; warp heads recompute;
        // thread 0 has it as prev_0.
        float carryA = __shfl_up_sync(0xffffffffu, xa[E - 1], 1);
        float carryB = __shfl_up_sync(0xffffffffu, xb[E - 1], 1);
        if (t == 0) {
            carryA = prevA; carryB = prevB;
        } else if (warp_head) {
            carryA = fmaf(sprev, sxe[buf][0][w - 1], cprev * prevA);
            carryB = fmaf(sprev, sxe[buf][1][w - 1], cprev * prevB);
        }

        float* yrA = y + (base + r) * NN;
        float4 oa0, oa1;
        oa0.x = carryA; oa0.y = xa[0]; oa0.z = xa[1]; oa0.w = xa[2];
        oa1.x = xa[3];  oa1.y = xa[4]; oa1.z = xa[5]; oa1.w = xa[6];
        __stcs(reinterpret_cast<float4*>(yrA + lo), oa0);
        __stcs(reinterpret_cast<float4*>(yrA + lo) + 1, oa1);
        if (hasB) {
            float* yrB = y + (base + r + 1) * NN;
            float4 ob0, ob1;
            ob0.x = carryB; ob0.y = xb[0]; ob0.z = xb[1]; ob0.w = xb[2];
            ob1.x = xb[3];  ob1.y = xb[4]; ob1.z = xb[5]; ob1.w = xb[6];
            __stcs(reinterpret_cast<float4*>(yrB + lo), ob0);
            __stcs(reinterpret_cast<float4*>(yrB + lo) + 1, ob1);
        }
    }
}

extern "C" void kernel_launch(void* const* d_in, const int* in_sizes, int n_in,
                              void* d_out, int out_size) {
    const float* x   = (const float*)d_in[0];   // (B, N) fp32
    const float* ang = (const float*)d_in[1];   // (N,)  fp32
    float* y = (float*)d_out;                   // (B, N) fp32

    const int rows   = out_size / NN;           // B = 16384
    const int blocks = (rows + R - 1) / R;      // 4096
    givens_kernel<<<blocks, T>>>(x, ang, y, rows);
}